// round 5
// baseline (speedup 1.0000x reference)
#include <cuda_runtime.h>

#define TT   2048
#define HB   128
#define NL   3
#define GCTA 32
#define NJ   4
#define NR   16

// Layer 0: K = 8(pad) + 128 = 136 ; layers 1,2: K = 256
#define WOFF0 0
#define WOFF1 (GCTA*NR*136)
#define WOFF2 (WOFF1 + GCTA*NR*256)
#define WTOT  (WOFF2 + GCTA*NR*256)

// h history: layer l, slot s (= h after step s-1; slot 0 = zeros), [hidden j][batch b]
__device__ float g_H[(size_t)NL * (TT + 1) * HB * HB];
__device__ float g_xT[TT * 8 * HB];
__device__ float g_Wp[WTOT];
__device__ float g_bias[NL * GCTA * NR];
__device__ int   g_flags[NL * TT];

typedef unsigned long long ull;

__device__ __forceinline__ ull pk2(float lo, float hi) {
    ull r; asm("mov.b64 %0,{%1,%2};" : "=l"(r) : "f"(lo), "f"(hi)); return r;
}
__device__ __forceinline__ void upk2(ull v, float& lo, float& hi) {
    asm("mov.b64 {%0,%1},%2;" : "=f"(lo), "=f"(hi) : "l"(v));
}
__device__ __forceinline__ ull ffma2(ull a, ull b, ull c) {
    ull d; asm("fma.rn.f32x2 %0,%1,%2,%3;" : "=l"(d) : "l"(a), "l"(b), "l"(c));
    return d;
}
__device__ __forceinline__ int ldacq(const int* p) {
    int v; asm volatile("ld.acquire.gpu.global.b32 %0,[%1];" : "=r"(v) : "l"(p) : "memory");
    return v;
}
__device__ __forceinline__ void red_release(int* p) {
    asm volatile("red.release.gpu.global.add.s32 [%0],1;" :: "l"(p) : "memory");
}
__device__ __forceinline__ float sigf(float x) {
    return __fdividef(1.0f, 1.0f + __expf(-x));
}
__device__ __forceinline__ float tanhf_fast(float x) {
    return __fdividef(2.0f, 1.0f + __expf(-2.0f * x)) - 1.0f;
}

// ---- pack weights/bias into per-CTA layout: row r=q*4+jj <-> gate row q*128+(g*4+jj)
__global__ void pack_kernel(
    const float* __restrict__ Wih0, const float* __restrict__ Whh0,
    const float* __restrict__ bih0, const float* __restrict__ bhh0,
    const float* __restrict__ Wih1, const float* __restrict__ Whh1,
    const float* __restrict__ bih1, const float* __restrict__ bhh1,
    const float* __restrict__ Wih2, const float* __restrict__ Whh2,
    const float* __restrict__ bih2, const float* __restrict__ bhh2)
{
    int blk = blockIdx.x;
    int l = blk / GCTA, g = blk % GCTA;
    const float* Wih = (l == 0) ? Wih0 : ((l == 1) ? Wih1 : Wih2);
    const float* Whh = (l == 0) ? Whh0 : ((l == 1) ? Whh1 : Whh2);
    const float* bih = (l == 0) ? bih0 : ((l == 1) ? bih1 : bih2);
    const float* bhh = (l == 0) ? bhh0 : ((l == 1) ? bhh1 : bhh2);

    int KA = (l == 0) ? 8 : 128;
    int KP = KA + 128;
    int base = ((l == 0) ? WOFF0 : ((l == 1) ? WOFF1 : WOFF2)) + g * NR * KP;

    for (int idx = threadIdx.x; idx < NR * KP; idx += blockDim.x) {
        int r = idx / KP, k = idx % KP;
        int q = r >> 2, jj = r & 3;
        int R = q * 128 + (g * NJ + jj);
        float v;
        if (k < KA) v = (l == 0) ? ((k < 6) ? Wih[R * 6 + k] : 0.0f)
                                 : Wih[R * 128 + k];
        else        v = Whh[R * 128 + (k - KA)];
        g_Wp[base + idx] = v;
    }
    if (threadIdx.x < NR) {
        int r = threadIdx.x, q = r >> 2, jj = r & 3;
        int R = q * 128 + (g * NJ + jj);
        g_bias[(l * GCTA + g) * NR + r] = bih[R] + bhh[R];
    }
}

// ---- transpose x -> xT[t][i pad 8][b]; zero h slot 0 per layer; zero flags
__global__ void prep_kernel(const float* __restrict__ x)
{
    int blk = blockIdx.x, tid = threadIdx.x;
    if (blk < TT) {
        int t = blk;
        #pragma unroll
        for (int i = 0; i < 8; i++) {
            float v = (i < 6) ? x[(size_t)tid * (TT * 6) + t * 6 + i] : 0.0f;
            g_xT[(t * 8 + i) * HB + tid] = v;
        }
    } else if (blk < TT + NL) {
        size_t base = (size_t)(blk - TT) * (TT + 1) * HB * HB;
        for (int i = tid; i < HB * HB; i += 128) g_H[base + i] = 0.0f;
    } else {
        for (int i = tid; i < NL * TT; i += 128) g_flags[i] = 0;
    }
}

// ---- persistent main kernel: 96 CTAs, 256 threads.
// warp = kh*4 + bg ; kh: K-half (0 = input/below-h + bias, 1 = own h(t-1)) ;
// bg: 32-batch group ; lane = batch within group.
__global__ void __launch_bounds__(256, 1) lstm_kernel()
{
    __shared__ __align__(16) float Wsm[NR * 256];
    __shared__ float red[NR * HB];
    __shared__ float bsm[NR];

    const int blk  = blockIdx.x;
    const int l    = blk / GCTA;
    const int g    = blk % GCTA;
    const int tid  = threadIdx.x;
    const int lane = tid & 31;
    const int warp = tid >> 5;
    const int bg   = warp & 3;
    const int kh   = warp >> 2;
    const int b    = bg * 32 + lane;

    const int KA = (l == 0) ? 8 : 128;
    const int KP = KA + 128;
    const int wbase = ((l == 0) ? WOFF0 : ((l == 1) ? WOFF1 : WOFF2)) + g * NR * KP;

    for (int idx = tid; idx < NR * KP; idx += 256) Wsm[idx] = g_Wp[wbase + idx];
    if (tid < NR) bsm[tid] = g_bias[(l * GCTA + g) * NR + tid];
    __syncthreads();

    const int Kw   = (kh == 0) ? KA : 128;
    const int woff = (kh == 0) ? 0 : KA;
    const int jg   = g * NJ;

    float c[NJ];
    #pragma unroll
    for (int jj = 0; jj < NJ; jj++) c[jj] = 0.0f;

    for (int t = 0; t < TT; t++) {
        // gate: own layer step t-1 done; layer below step t done
        if (tid == 0) {
            if (t > 0) { const int* f = &g_flags[l * TT + t - 1];
                         while (ldacq(f) < GCTA) {} }
            if (l > 0) { const int* f = &g_flags[(l - 1) * TT + t];
                         while (ldacq(f) < GCTA) {} }
        }
        __syncthreads();

        const float* __restrict__ S;
        if (kh == 0)
            S = (l == 0) ? (g_xT + (size_t)t * 8 * HB)
                         : (g_H + (size_t)((l - 1) * (TT + 1) + t + 1) * HB * HB);
        else
            S = g_H + (size_t)(l * (TT + 1) + t) * HB * HB;

        ull acc[NR];
        #pragma unroll
        for (int r = 0; r < NR; r++)
            acc[r] = (kh == 0) ? pk2(bsm[r], 0.0f) : 0ULL;

        #pragma unroll 4
        for (int k = 0; k < Kw; k += 4) {
            float a0 = __ldcg(S + (k + 0) * HB + b);
            float a1 = __ldcg(S + (k + 1) * HB + b);
            float a2 = __ldcg(S + (k + 2) * HB + b);
            float a3 = __ldcg(S + (k + 3) * HB + b);
            ull h01 = pk2(a0, a1);
            ull h23 = pk2(a2, a3);
            const float* wrow = Wsm + woff + k;
            #pragma unroll
            for (int r = 0; r < NR; r++) {
                ulonglong2 w = *(const ulonglong2*)(wrow + r * KP); // LDS.128 bcast
                acc[r] = ffma2(w.x, h01, acc[r]);
                acc[r] = ffma2(w.y, h23, acc[r]);
            }
        }

        if (kh == 1) {
            #pragma unroll
            for (int r = 0; r < NR; r++) {
                float lo, hi; upk2(acc[r], lo, hi);
                red[r * HB + b] = lo + hi;
            }
        }
        __syncthreads();

        if (kh == 0) {
            float gate[NR];
            #pragma unroll
            for (int r = 0; r < NR; r++) {
                float lo, hi; upk2(acc[r], lo, hi);
                gate[r] = lo + hi + red[r * HB + b];
            }
            float* Hout = g_H + (size_t)(l * (TT + 1) + t + 1) * HB * HB;
            #pragma unroll
            for (int jj = 0; jj < NJ; jj++) {
                float iv = sigf(gate[jj]);
                float fv = sigf(gate[4 + jj]);
                float gv = tanhf_fast(gate[8 + jj]);
                float ov = sigf(gate[12 + jj]);
                c[jj] = fv * c[jj] + iv * gv;
                __stcg(Hout + (jg + jj) * HB + b, ov * tanhf_fast(c[jj]));
            }
        }
        __threadfence();
        __syncthreads();
        if (tid == 0) red_release(&g_flags[l * TT + t]);
    }
}

// ---- head: out[b] = h2[T-1][:,b] . W_out + b_out
__global__ void head_kernel(const float* __restrict__ W_out,
                            const float* __restrict__ b_out,
                            float* __restrict__ out)
{
    int b = threadIdx.x;
    const float* h = g_H + (size_t)(2 * (TT + 1) + TT) * HB * HB;
    float s = b_out[0];
    #pragma unroll 8
    for (int j = 0; j < HB; j++) s += h[j * HB + b] * W_out[j];
    out[b] = s;
}

extern "C" void kernel_launch(void* const* d_in, const int* in_sizes, int n_in,
                              void* d_out, int out_size)
{
    (void)in_sizes; (void)n_in; (void)out_size;
    const float* x = (const float*)d_in[0];
    pack_kernel<<<NL * GCTA, 256>>>(
        (const float*)d_in[1], (const float*)d_in[2],
        (const float*)d_in[3], (const float*)d_in[4],
        (const float*)d_in[5], (const float*)d_in[6],
        (const float*)d_in[7], (const float*)d_in[8],
        (const float*)d_in[9], (const float*)d_in[10],
        (const float*)d_in[11], (const float*)d_in[12]);
    prep_kernel<<<TT + NL + 1, 128>>>(x);
    lstm_kernel<<<NL * GCTA, 256>>>();
    head_kernel<<<1, 128>>>((const float*)d_in[13], (const float*)d_in[14],
                            (float*)d_out);
}

// round 6
// speedup vs baseline: 1.2077x; 1.2077x over previous
#include <cuda_runtime.h>

#define TT   2048
#define HB   128
#define NL   3
#define GCTA 32
#define NJ   4
#define NR   16

// Layer 0: K = 8(pad) + 128 = 136 ; layers 1,2: K = 256
#define WOFF0 0
#define WOFF1 (GCTA*NR*136)
#define WOFF2 (WOFF1 + GCTA*NR*256)
#define WTOT  (WOFF2 + GCTA*NR*256)

// h history: layer l, slot s (= h after step s-1; slot 0 = zeros), [hidden j][batch b]
__device__ float g_H[(size_t)NL * (TT + 1) * HB * HB];
__device__ float g_xT[TT * 8 * HB];
__device__ float g_Wp[WTOT];
__device__ float g_bias[NL * GCTA * NR];
__device__ int   g_flags[NL * TT];

typedef unsigned long long ull;

__device__ __forceinline__ ull pk2(float lo, float hi) {
    ull r; asm("mov.b64 %0,{%1,%2};" : "=l"(r) : "f"(lo), "f"(hi)); return r;
}
__device__ __forceinline__ void upk2(ull v, float& lo, float& hi) {
    asm("mov.b64 {%0,%1},%2;" : "=f"(lo), "=f"(hi) : "l"(v));
}
__device__ __forceinline__ ull ffma2(ull a, ull b, ull c) {
    ull d; asm("fma.rn.f32x2 %0,%1,%2,%3;" : "=l"(d) : "l"(a), "l"(b), "l"(c));
    return d;
}
__device__ __forceinline__ int ldacq(const int* p) {
    int v; asm volatile("ld.acquire.gpu.global.b32 %0,[%1];" : "=r"(v) : "l"(p) : "memory");
    return v;
}
__device__ __forceinline__ void red_release(int* p) {
    asm volatile("red.release.gpu.global.add.s32 [%0],1;" :: "l"(p) : "memory");
}
__device__ __forceinline__ float sigf(float x) {
    return __fdividef(1.0f, 1.0f + __expf(-x));
}
__device__ __forceinline__ float tanhf_fast(float x) {
    return __fdividef(2.0f, 1.0f + __expf(-2.0f * x)) - 1.0f;
}

// ---- pack weights/bias: row r=q*4+jj <-> gate row q*128+(g*4+jj); cols [0,KA)=W_ih (l0 pad 6->8), [KA,KP)=W_hh
__global__ void pack_kernel(
    const float* __restrict__ Wih0, const float* __restrict__ Whh0,
    const float* __restrict__ bih0, const float* __restrict__ bhh0,
    const float* __restrict__ Wih1, const float* __restrict__ Whh1,
    const float* __restrict__ bih1, const float* __restrict__ bhh1,
    const float* __restrict__ Wih2, const float* __restrict__ Whh2,
    const float* __restrict__ bih2, const float* __restrict__ bhh2)
{
    int blk = blockIdx.x;
    int l = blk / GCTA, g = blk % GCTA;
    const float* Wih = (l == 0) ? Wih0 : ((l == 1) ? Wih1 : Wih2);
    const float* Whh = (l == 0) ? Whh0 : ((l == 1) ? Whh1 : Whh2);
    const float* bih = (l == 0) ? bih0 : ((l == 1) ? bih1 : bih2);
    const float* bhh = (l == 0) ? bhh0 : ((l == 1) ? bhh1 : bhh2);

    int KA = (l == 0) ? 8 : 128;
    int KP = KA + 128;
    int base = ((l == 0) ? WOFF0 : ((l == 1) ? WOFF1 : WOFF2)) + g * NR * KP;

    for (int idx = threadIdx.x; idx < NR * KP; idx += blockDim.x) {
        int r = idx / KP, k = idx % KP;
        int q = r >> 2, jj = r & 3;
        int R = q * 128 + (g * NJ + jj);
        float v;
        if (k < KA) v = (l == 0) ? ((k < 6) ? Wih[R * 6 + k] : 0.0f)
                                 : Wih[R * 128 + k];
        else        v = Whh[R * 128 + (k - KA)];
        g_Wp[base + idx] = v;
    }
    if (threadIdx.x < NR) {
        int r = threadIdx.x, q = r >> 2, jj = r & 3;
        int R = q * 128 + (g * NJ + jj);
        g_bias[(l * GCTA + g) * NR + r] = bih[R] + bhh[R];
    }
}

// ---- transpose x -> xT[t][i pad 8][b]; zero h slot 0 per layer; zero flags
__global__ void prep_kernel(const float* __restrict__ x)
{
    int blk = blockIdx.x, tid = threadIdx.x;
    if (blk < TT) {
        int t = blk;
        #pragma unroll
        for (int i = 0; i < 8; i++) {
            float v = (i < 6) ? x[(size_t)tid * (TT * 6) + t * 6 + i] : 0.0f;
            g_xT[(t * 8 + i) * HB + tid] = v;
        }
    } else if (blk < TT + NL) {
        size_t base = (size_t)(blk - TT) * (TT + 1) * HB * HB;
        for (int i = tid; i < HB * HB; i += 128) g_H[base + i] = 0.0f;
    } else {
        for (int i = tid; i < NL * TT; i += 128) g_flags[i] = 0;
    }
}

// ---- compile-time GEMM slice: acc2[r] += W[r][k..]*src[k..][b] over k in [S,E)
// Region A (k < KA): source SA (x or below-layer h). Region B: SB (own h(t-1)).
template<int KP, int KA, int S, int E, bool BIAS>
__device__ __forceinline__ void gemm_slice(
    const float* __restrict__ SA, const float* __restrict__ SB,
    const float* __restrict__ Wsm, const float* __restrict__ bsm,
    int b, ull* acc)
{
    #pragma unroll
    for (int r = 0; r < NR; r++)
        acc[r] = BIAS ? pk2(bsm[r], 0.0f) : 0ULL;

    if constexpr (S < KA) {
        constexpr int AE = (E < KA) ? E : KA;
        #pragma unroll 4
        for (int k = S; k < AE; k += 4) {
            float a0 = __ldcg(SA + (k + 0) * HB + b);
            float a1 = __ldcg(SA + (k + 1) * HB + b);
            float a2 = __ldcg(SA + (k + 2) * HB + b);
            float a3 = __ldcg(SA + (k + 3) * HB + b);
            ull h01 = pk2(a0, a1), h23 = pk2(a2, a3);
            const float* wrow = Wsm + k;
            #pragma unroll
            for (int r = 0; r < NR; r++) {
                ulonglong2 w = *(const ulonglong2*)(wrow + r * KP); // LDS.128 bcast, imm offset
                acc[r] = ffma2(w.x, h01, acc[r]);
                acc[r] = ffma2(w.y, h23, acc[r]);
            }
        }
    }
    if constexpr (E > KA) {
        constexpr int BS = (S > KA) ? S : KA;
        #pragma unroll 4
        for (int k = BS; k < E; k += 4) {
            float a0 = __ldcg(SB + (k - KA + 0) * HB + b);
            float a1 = __ldcg(SB + (k - KA + 1) * HB + b);
            float a2 = __ldcg(SB + (k - KA + 2) * HB + b);
            float a3 = __ldcg(SB + (k - KA + 3) * HB + b);
            ull h01 = pk2(a0, a1), h23 = pk2(a2, a3);
            const float* wrow = Wsm + k;
            #pragma unroll
            for (int r = 0; r < NR; r++) {
                ulonglong2 w = *(const ulonglong2*)(wrow + r * KP);
                acc[r] = ffma2(w.x, h01, acc[r]);
                acc[r] = ffma2(w.y, h23, acc[r]);
            }
        }
    }
}

// ---- per-layer persistent body. 512 threads: warp = kq*4+bg, kq = K-quarter,
// bg = 32-batch group, lane = batch. kq0 carries bias + activations + c state.
template<int L>
__device__ __forceinline__ void lstm_run(int g, float* Wsm, float* redm, float* bsm)
{
    constexpr int KA = (L == 0) ? 8 : 128;
    constexpr int KP = KA + 128;
    constexpr int WOFF = (L == 0) ? WOFF0 : ((L == 1) ? WOFF1 : WOFF2);
    constexpr int SL1 = (L == 0) ? 40 : 64;
    constexpr int SL2 = (L == 0) ? 72 : 128;
    constexpr int SL3 = (L == 0) ? 104 : 192;

    const int tid  = threadIdx.x;
    const int lane = tid & 31;
    const int warp = tid >> 5;
    const int bg   = warp & 3;
    const int kq   = warp >> 2;
    const int b    = bg * 32 + lane;
    const int jg   = g * NJ;

    const int wbase = WOFF + g * NR * KP;
    for (int i = tid; i < NR * KP; i += 512) Wsm[i] = g_Wp[wbase + i];
    if (tid < NR) bsm[tid] = g_bias[(L * GCTA + g) * NR + tid];
    __syncthreads();

    float c0 = 0, c1 = 0, c2 = 0, c3 = 0;

    for (int t = 0; t < TT; t++) {
        if (tid == 0 && t > 0) {
            const int* f = &g_flags[L * TT + t - 1];
            while (ldacq(f) < GCTA) {}
        }
        if (tid == 32 && L > 0) {
            const int* f = &g_flags[(L - 1) * TT + t];
            while (ldacq(f) < GCTA) {}
        }
        __syncthreads();

        const float* SA = (L == 0)
            ? (g_xT + (size_t)t * 8 * HB)
            : (g_H + (size_t)((L - 1) * (TT + 1) + t + 1) * HB * HB);
        const float* SB = g_H + (size_t)(L * (TT + 1) + t) * HB * HB;

        ull acc[NR];
        switch (kq) {
        case 0:  gemm_slice<KP, KA, 0,   SL1, true >(SA, SB, Wsm, bsm, b, acc); break;
        case 1:  gemm_slice<KP, KA, SL1, SL2, false>(SA, SB, Wsm, bsm, b, acc); break;
        case 2:  gemm_slice<KP, KA, SL2, SL3, false>(SA, SB, Wsm, bsm, b, acc); break;
        default: gemm_slice<KP, KA, SL3, KP,  false>(SA, SB, Wsm, bsm, b, acc); break;
        }

        if (kq > 0) {
            #pragma unroll
            for (int r = 0; r < NR; r++) {
                float lo, hi; upk2(acc[r], lo, hi);
                redm[(kq - 1) * NR * HB + r * HB + b] = lo + hi;
            }
        }
        __syncthreads();

        if (kq == 0) {
            float gate[NR];
            #pragma unroll
            for (int r = 0; r < NR; r++) {
                float lo, hi; upk2(acc[r], lo, hi);
                gate[r] = lo + hi
                        + redm[r * HB + b]
                        + redm[NR * HB + r * HB + b]
                        + redm[2 * NR * HB + r * HB + b];
            }
            float* Hout = g_H + (size_t)(L * (TT + 1) + t + 1) * HB * HB;
            float cc[4] = {c0, c1, c2, c3};
            #pragma unroll
            for (int jj = 0; jj < 4; jj++) {
                float iv = sigf(gate[jj]);
                float fv = sigf(gate[4 + jj]);
                float gv = tanhf_fast(gate[8 + jj]);
                float ov = sigf(gate[12 + jj]);
                cc[jj] = fv * cc[jj] + iv * gv;
                __stcg(Hout + (jg + jj) * HB + b, ov * tanhf_fast(cc[jj]));
            }
            c0 = cc[0]; c1 = cc[1]; c2 = cc[2]; c3 = cc[3];
        }
        __syncthreads();
        if (tid == 0) {
            asm volatile("fence.acq_rel.gpu;" ::: "memory");
            red_release(&g_flags[L * TT + t]);
        }
    }
}

__global__ void __launch_bounds__(512, 1) lstm_kernel()
{
    __shared__ __align__(16) float Wsm[NR * 256];   // 16 KB
    __shared__ float redm[3 * NR * HB];             // 24 KB
    __shared__ float bsm[NR];

    const int blk = blockIdx.x;
    const int l = blk >> 5, g = blk & 31;
    if (l == 0)      lstm_run<0>(g, Wsm, redm, bsm);
    else if (l == 1) lstm_run<1>(g, Wsm, redm, bsm);
    else             lstm_run<2>(g, Wsm, redm, bsm);
}

// ---- head: out[b] = h2[T-1][:,b] . W_out + b_out
__global__ void head_kernel(const float* __restrict__ W_out,
                            const float* __restrict__ b_out,
                            float* __restrict__ out)
{
    int b = threadIdx.x;
    const float* h = g_H + (size_t)(2 * (TT + 1) + TT) * HB * HB;
    float s = b_out[0];
    #pragma unroll 8
    for (int j = 0; j < HB; j++) s += h[j * HB + b] * W_out[j];
    out[b] = s;
}

extern "C" void kernel_launch(void* const* d_in, const int* in_sizes, int n_in,
                              void* d_out, int out_size)
{
    (void)in_sizes; (void)n_in; (void)out_size;
    const float* x = (const float*)d_in[0];
    pack_kernel<<<NL * GCTA, 256>>>(
        (const float*)d_in[1], (const float*)d_in[2],
        (const float*)d_in[3], (const float*)d_in[4],
        (const float*)d_in[5], (const float*)d_in[6],
        (const float*)d_in[7], (const float*)d_in[8],
        (const float*)d_in[9], (const float*)d_in[10],
        (const float*)d_in[11], (const float*)d_in[12]);
    prep_kernel<<<TT + NL + 1, 128>>>(x);
    lstm_kernel<<<NL * GCTA, 512>>>();
    head_kernel<<<1, 128>>>((const float*)d_in[13], (const float*)d_in[14],
                            (float*)d_out);
}